// round 11
// baseline (speedup 1.0000x reference)
#include <cuda_runtime.h>
#include <cuda_fp16.h>

// Problem constants (fixed by the dataset's reference_code)
#define HW_DIM     512
#define NB         6
#define NLOOPS     4
#define NDET       4096
#define NSAMP      128
#define NBATCH     4
#define NPTS       (NDET * NSAMP)          // 524288
#define PIX        (512 * 512)             // per-channel elements
#define B_STRIDE   (2 * NB * PIX)          // per-batch elements (12 channels)

#define REFINE_BLOCKS  (NPTS / 256)                   // 2048
#define REPACK_BLOCKS  (NBATCH * NB * PIX / 8 / 256)  // 3072

// fp16-packed refinement: [BATCH][NB][H][W] of half2(x,y) = 25.2 MB
__device__ __half2 g_packed[NBATCH * NB * PIX];
// det after iteration 1 (exact f32)
__device__ float2  g_mid[NPTS];

// ---------------------------------------------------------------------------
// Kernel A: two independent jobs in one launch, overlapped by the scheduler.
//   blocks [0, REFINE_BLOCKS):  iteration 1 in exact f32 on the ORIGINAL
//                               layout (no dependence on g_packed)
//   blocks [REFINE_BLOCKS, +REPACK_BLOCKS): repack f32 -> half2 (75 MB traffic)
// Both are memory-throughput bound; neither waits on the other.
// ---------------------------------------------------------------------------
__global__ void __launch_bounds__(256)
fused_a_kernel(const float* __restrict__ det_in,
               const float* __restrict__ refinement,
               const float* __restrict__ sampling,
               const int*   __restrict__ bvec)
{
    if (blockIdx.x < REFINE_BLOCKS) {
        // ---- refine, iteration 1 only (no early exit possible) ----
        const int t = blockIdx.x * 256 + threadIdx.x;
        const int s = t & (NSAMP - 1);
        const int d = t >> 7;

        // Per-sample bucket setup — reference arithmetic exactly.
        const float base = sampling[s] * (float)NB;
        const float bif  = floorf(base);
        const int   bint = (int)bif;

        const float d0 = fabsf(bif - base);
        const float w0 = (d0 > 1.0f) ? 0.0f : (1.0f - d0);
        const float d1 = fabsf((bif + 1.0f) - base);
        const float w1 = (d1 > 1.0f) ? 0.0f : (1.0f - d1);

        const int c0 = (bint % NB) * 2;
        const int c1 = ((bint + 1) % NB) * 2;

        const float* __restrict__ refb = refinement + (long)bvec[d] * B_STRIDE;
        const float* __restrict__ p0x  = refb + (long)c0 * PIX;
        const float* __restrict__ p1x  = refb + (long)c1 * PIX;

        const float2 det = reinterpret_cast<const float2*>(det_in)[t];
        float xr = rintf(det.x);             // round-half-even == jnp.round
        float yr = rintf(det.y);
        xr = fminf(fmaxf(xr, 0.0f), (float)(HW_DIM - 1));
        yr = fminf(fmaxf(yr, 0.0f), (float)(HW_DIM - 1));
        const int pix = (int)yr * HW_DIM + (int)xr;

        const float r0x = __ldg(p0x + pix);
        const float r0y = __ldg(p0x + PIX + pix);
        const float r1x = __ldg(p1x + pix);
        const float r1y = __ldg(p1x + PIX + pix);

        g_mid[t] = make_float2(xr + (w0 * r0x + w1 * r1x),
                               yr + (w0 * r0y + w1 * r1y));
    } else {
        // ---- repack: 8 pixels per thread (proven 8.9 us standalone) ----
        const int t     = (blockIdx.x - REFINE_BLOCKS) * 256 + threadIdx.x;
        const int oct   = t % (PIX / 8);
        const int slice = t / (PIX / 8);     // b*NB + k
        const int p     = oct * 8;

        const int b = slice / NB;
        const int k = slice - b * NB;

        const float* ch0 = refinement + (long)b * B_STRIDE + (long)(2 * k)     * PIX;
        const float* ch1 = refinement + (long)b * B_STRIDE + (long)(2 * k + 1) * PIX;

        const float4 x0 = *reinterpret_cast<const float4*>(ch0 + p);
        const float4 x1 = *reinterpret_cast<const float4*>(ch0 + p + 4);
        const float4 y0 = *reinterpret_cast<const float4*>(ch1 + p);
        const float4 y1 = *reinterpret_cast<const float4*>(ch1 + p + 4);

        __half2 h[8];
        h[0] = __floats2half2_rn(x0.x, y0.x);
        h[1] = __floats2half2_rn(x0.y, y0.y);
        h[2] = __floats2half2_rn(x0.z, y0.z);
        h[3] = __floats2half2_rn(x0.w, y0.w);
        h[4] = __floats2half2_rn(x1.x, y1.x);
        h[5] = __floats2half2_rn(x1.y, y1.y);
        h[6] = __floats2half2_rn(x1.z, y1.z);
        h[7] = __floats2half2_rn(x1.w, y1.w);

        uint4* dst = reinterpret_cast<uint4*>(&g_packed[(long)slice * PIX + p]);
        dst[0] = *reinterpret_cast<const uint4*>(&h[0]);
        dst[1] = *reinterpret_cast<const uint4*>(&h[4]);
    }
}

// ---------------------------------------------------------------------------
// Kernel B: iterations 2..4 on the fp16 packed volume (2x 4B loads/iter),
// ILP=1 (proven best), exact fixed-point and 2-cycle early exits.
// Entry state reconstructed: det_0 from det_in, det_1 from g_mid,
// prev1 = pix_0 recomputed, prev2 = -1, (px,py) = det_0.
// ---------------------------------------------------------------------------
__global__ void __launch_bounds__(256)
refine_b_kernel(const float* __restrict__ det_in,
                const float* __restrict__ sampling,
                const int*   __restrict__ bvec,
                float*       __restrict__ out)
{
    const int t = blockIdx.x * 256 + threadIdx.x;
    const int s = t & (NSAMP - 1);
    const int d = t >> 7;

    // Per-sample bucket setup — reference arithmetic exactly.
    const float base = sampling[s] * (float)NB;
    const float bif  = floorf(base);
    const int   bint = (int)bif;

    const float d0 = fabsf(bif - base);
    const float w0 = (d0 > 1.0f) ? 0.0f : (1.0f - d0);
    const float d1 = fabsf((bif + 1.0f) - base);
    const float w1 = (d1 > 1.0f) ? 0.0f : (1.0f - d1);

    const int k0 = bint % NB;
    const int k1 = (bint + 1) % NB;
    const int bb = bvec[d] * NB;
    const __half2* __restrict__ p0 = g_packed + (long)(bb + k0) * PIX;
    const __half2* __restrict__ p1 = g_packed + (long)(bb + k1) * PIX;

    // Reconstruct iteration-1 state
    const float2 det0 = reinterpret_cast<const float2*>(det_in)[t];
    float xr0 = rintf(det0.x);
    float yr0 = rintf(det0.y);
    xr0 = fminf(fmaxf(xr0, 0.0f), (float)(HW_DIM - 1));
    yr0 = fminf(fmaxf(yr0, 0.0f), (float)(HW_DIM - 1));
    const int pix0 = (int)yr0 * HW_DIM + (int)xr0;

    const float2 det1 = g_mid[t];
    float x = det1.x, y = det1.y;
    float px = det0.x, py = det0.y;          // det_{l-1} entering l=1
    int prev1 = pix0, prev2 = -1;

    #pragma unroll
    for (int l = 1; l < NLOOPS; ++l) {
        float xr = rintf(x);                 // round-half-even == jnp.round
        float yr = rintf(y);
        xr = fminf(fmaxf(xr, 0.0f), (float)(HW_DIM - 1));
        yr = fminf(fmaxf(yr, 0.0f), (float)(HW_DIM - 1));
        const int pix = (int)yr * HW_DIM + (int)xr;

        if (pix == prev1) break;             // fixed point
        if (pix == prev2) {                  // 2-cycle
            if ((NLOOPS - l) & 1) { x = px; y = py; }
            break;
        }
        prev2 = prev1;  prev1 = pix;
        px = x;  py = y;

        const float2 g0 = __half22float2(__ldg(p0 + pix));
        const float2 g1 = __half22float2(__ldg(p1 + pix));

        x = xr + (w0 * g0.x + w1 * g1.x);
        y = yr + (w0 * g0.y + w1 * g1.y);
    }

    reinterpret_cast<float2*>(out)[t] = make_float2(x, y);
}

extern "C" void kernel_launch(void* const* d_in, const int* in_sizes, int n_in,
                              void* d_out, int out_size)
{
    // Identify inputs by element count:
    //   det_indices : 1048576 f32, refinement : 12582912 f32,
    //   sampling : 128 f32, b : 4096 i32
    const float* det_in     = nullptr;
    const float* refinement = nullptr;
    const float* sampling   = nullptr;
    const int*   bvec       = nullptr;

    for (int i = 0; i < n_in; ++i) {
        switch (in_sizes[i]) {
            case 1048576:  det_in     = (const float*)d_in[i]; break;
            case 12582912: refinement = (const float*)d_in[i]; break;
            case 128:      sampling   = (const float*)d_in[i]; break;
            case 4096:     bvec       = (const int*)d_in[i];   break;
            default: break;
        }
    }

    fused_a_kernel<<<REFINE_BLOCKS + REPACK_BLOCKS, 256>>>(det_in, refinement,
                                                           sampling, bvec);
    refine_b_kernel<<<REFINE_BLOCKS, 256>>>(det_in, sampling, bvec,
                                            (float*)d_out);
}

// round 12
// speedup vs baseline: 1.2281x; 1.2281x over previous
#include <cuda_runtime.h>
#include <cuda_fp16.h>

// Problem constants (fixed by the dataset's reference_code)
#define HW_DIM     512
#define NB         6
#define NLOOPS     4
#define NDET       4096
#define NSAMP      128
#define NBATCH     4
#define NPTS       (NDET * NSAMP)          // 524288
#define PIX        (512 * 512)             // per-channel elements
#define B_STRIDE   (2 * NB * PIX)          // per-batch elements (12 channels)

// Packed refinement: [BATCH][NB][H][W] of half2(x,y) = 25.2 MB.
__device__ __half2 g_packed[NBATCH * NB * PIX];

// ---------------------------------------------------------------------------
// Kernel 1: repack f32 channel pairs -> half2 (75 MB total traffic).
// Proven at 8.9 us. Each thread: 8 pixels.
// ---------------------------------------------------------------------------
__global__ void __launch_bounds__(256)
repack_kernel(const float* __restrict__ refinement)
{
    const int t = blockIdx.x * blockDim.x + threadIdx.x;
    const int oct   = t % (PIX / 8);
    const int slice = t / (PIX / 8);        // b*NB + k
    const int p     = oct * 8;

    const int b = slice / NB;
    const int k = slice - b * NB;

    const float* ch0 = refinement + (long)b * B_STRIDE + (long)(2 * k)     * PIX;
    const float* ch1 = refinement + (long)b * B_STRIDE + (long)(2 * k + 1) * PIX;

    const float4 x0 = *reinterpret_cast<const float4*>(ch0 + p);
    const float4 x1 = *reinterpret_cast<const float4*>(ch0 + p + 4);
    const float4 y0 = *reinterpret_cast<const float4*>(ch1 + p);
    const float4 y1 = *reinterpret_cast<const float4*>(ch1 + p + 4);

    __half2 h[8];
    h[0] = __floats2half2_rn(x0.x, y0.x);
    h[1] = __floats2half2_rn(x0.y, y0.y);
    h[2] = __floats2half2_rn(x0.z, y0.z);
    h[3] = __floats2half2_rn(x0.w, y0.w);
    h[4] = __floats2half2_rn(x1.x, y1.x);
    h[5] = __floats2half2_rn(x1.y, y1.y);
    h[6] = __floats2half2_rn(x1.z, y1.z);
    h[7] = __floats2half2_rn(x1.w, y1.w);

    uint4* dst = reinterpret_cast<uint4*>(&g_packed[(long)slice * PIX + p]);
    dst[0] = *reinterpret_cast<const uint4*>(&h[0]);
    dst[1] = *reinterpret_cast<const uint4*>(&h[4]);
}

// ---------------------------------------------------------------------------
// Kernel 2: refine, 2x 4B gathers/iter, LEAN ILP=2 (minimal live state):
//  - rounded coords overwrite x/y (previous det already saved in px/py)
//  - prev1 doubles as the gather pixel index
//  - exact fixed-point and 2-cycle early exits
// ---------------------------------------------------------------------------
__global__ void __launch_bounds__(256)
refine_kernel(const float*  __restrict__ det_in,     // [NDET, NSAMP, 2]
              const float*  __restrict__ sampling,   // [NSAMP]
              const int*    __restrict__ bvec,       // [NDET]
              float*        __restrict__ out)        // [NDET, NSAMP, 2]
{
    const int t0 = blockIdx.x * 512 + threadIdx.x;   // points t0, t0+256

    float x[2], y[2], px[2], py[2], w0[2], w1[2];
    int   off0[2], off1[2], prev1[2], prev2[2];
    bool  done[2];

    #pragma unroll
    for (int i = 0; i < 2; ++i) {
        const int t = t0 + i * 256;
        const int s = t & (NSAMP - 1);
        const int d = t >> 7;

        // Per-sample bucket setup — reference arithmetic exactly.
        const float base = sampling[s] * (float)NB;
        const float bif  = floorf(base);
        const int   bint = (int)bif;

        const float d0 = fabsf(bif - base);
        w0[i] = (d0 > 1.0f) ? 0.0f : (1.0f - d0);
        const float d1 = fabsf((bif + 1.0f) - base);
        w1[i] = (d1 > 1.0f) ? 0.0f : (1.0f - d1);

        const int k0 = bint % NB;
        const int k1 = (bint + 1) % NB;
        const int bb = bvec[d] * NB;
        off0[i] = (bb + k0) * PIX;           // max ~6.3M, fits int
        off1[i] = (bb + k1) * PIX;

        const float2 det = reinterpret_cast<const float2*>(det_in)[t];
        x[i]  = det.x;  y[i]  = det.y;
        px[i] = det.x;  py[i] = det.y;
        prev1[i] = -1;  prev2[i] = -1;  done[i] = false;
    }

    #pragma unroll
    for (int l = 0; l < NLOOPS; ++l) {
        bool ld[2];

        // Phase A: round/clip, exit checks; on continue, save det into
        // px/py and put ROUNDED coords into x/y (consumed in phase C).
        #pragma unroll
        for (int i = 0; i < 2; ++i) {
            ld[i] = false;
            if (!done[i]) {
                float xr = rintf(x[i]);      // round-half-even == jnp.round
                float yr = rintf(y[i]);
                xr = fminf(fmaxf(xr, 0.0f), (float)(HW_DIM - 1));
                yr = fminf(fmaxf(yr, 0.0f), (float)(HW_DIM - 1));
                const int pix = (int)yr * HW_DIM + (int)xr;

                if (pix == prev1[i]) {               // fixed point
                    done[i] = true;
                } else if (pix == prev2[i]) {        // 2-cycle
                    if ((NLOOPS - l) & 1) { x[i] = px[i]; y[i] = py[i]; }
                    done[i] = true;
                } else {
                    prev2[i] = prev1[i];
                    prev1[i] = pix;                  // also the gather index
                    px[i] = x[i];  py[i] = y[i];
                    x[i]  = xr;    y[i]  = yr;
                    ld[i] = true;
                }
            }
        }

        // Phase B: issue all gathers together (up to 4 loads in flight)
        __half2 v0[2], v1[2];
        #pragma unroll
        for (int i = 0; i < 2; ++i) {
            if (ld[i]) {
                v0[i] = __ldg(g_packed + off0[i] + prev1[i]);
                v1[i] = __ldg(g_packed + off1[i] + prev1[i]);
            }
        }

        // Phase C: consume (x,y currently hold rounded coords)
        #pragma unroll
        for (int i = 0; i < 2; ++i) {
            if (ld[i]) {
                const float2 g0 = __half22float2(v0[i]);
                const float2 g1 = __half22float2(v1[i]);
                x[i] = x[i] + (w0[i] * g0.x + w1[i] * g1.x);
                y[i] = y[i] + (w0[i] * g0.y + w1[i] * g1.y);
            }
        }
    }

    #pragma unroll
    for (int i = 0; i < 2; ++i) {
        const int t = t0 + i * 256;
        reinterpret_cast<float2*>(out)[t] = make_float2(x[i], y[i]);
    }
}

extern "C" void kernel_launch(void* const* d_in, const int* in_sizes, int n_in,
                              void* d_out, int out_size)
{
    // Identify inputs by element count:
    //   det_indices : 1048576 f32, refinement : 12582912 f32,
    //   sampling : 128 f32, b : 4096 i32
    const float* det_in     = nullptr;
    const float* refinement = nullptr;
    const float* sampling   = nullptr;
    const int*   bvec       = nullptr;

    for (int i = 0; i < n_in; ++i) {
        switch (in_sizes[i]) {
            case 1048576:  det_in     = (const float*)d_in[i]; break;
            case 12582912: refinement = (const float*)d_in[i]; break;
            case 128:      sampling   = (const float*)d_in[i]; break;
            case 4096:     bvec       = (const int*)d_in[i];   break;
            default: break;
        }
    }

    {
        const int total = NBATCH * NB * (PIX / 8);     // 786432 threads
        repack_kernel<<<total / 256, 256>>>(refinement);
    }
    refine_kernel<<<NPTS / 512, 256>>>(det_in, sampling, bvec, (float*)d_out);
}